// round 12
// baseline (speedup 1.0000x reference)
#include <cuda_runtime.h>
#include <cuda_fp16.h>
#include <cstdint>

#define DINL __device__ __forceinline__

namespace {
constexpr int NQ   = 3600;    // B*Q
constexpr int KD   = 256;     // query dim
constexpr int NPAR = 32768;   // G * TOTAL
constexpr int TOT  = 8192;
constexpr int SPLITK = 8;
constexpr int WN_ELEMS = 8388608;         // 256*32768 == 32768*256
// K2 smem layout (halfs): per group M[64][72], S[128][40], X/H[32][72]
constexpr int G_M = 64 * 72;              // 4608
constexpr int G_S = 128 * 40;             // 5120
constexpr int G_X = 32 * 72;              // 2304
constexpr int GSTR = G_M + G_S + G_X;     // 12032 halfs
constexpr int K2_SMEM = 2 * GSTR * 2;     // 48128 bytes  (<= 49152 default limit)
}

// scratch (device globals: allocation-free)
__device__ __half g_params[(size_t)NQ * NPAR];              // 236 MB
__device__ __half g_h2[(size_t)NQ * NPAR];                  // 236 MB
__device__ float  g_psum[(size_t)SPLITK * NQ * KD];         // 29.5 MB
__device__ __half g_wp_h[(size_t)WN_ELEMS];                 // 16.7 MB
__device__ __half g_wo_h[(size_t)WN_ELEMS];                 // 16.7 MB
__device__ __half g_q_h[(size_t)NQ * KD];                   // 1.8 MB

DINL uint32_t smem_u32(const void* p){ return (uint32_t)__cvta_generic_to_shared(p); }

DINL void ldsm_x4(uint32_t r[4], uint32_t a){
    asm volatile("ldmatrix.sync.aligned.m8n8.x4.shared.b16 {%0,%1,%2,%3}, [%4];"
                 : "=r"(r[0]),"=r"(r[1]),"=r"(r[2]),"=r"(r[3]) : "r"(a));
}
DINL void ldsm_x4_t(uint32_t r[4], uint32_t a){
    asm volatile("ldmatrix.sync.aligned.m8n8.x4.trans.shared.b16 {%0,%1,%2,%3}, [%4];"
                 : "=r"(r[0]),"=r"(r[1]),"=r"(r[2]),"=r"(r[3]) : "r"(a));
}
DINL void mma16816(float d[4], const uint32_t a[4], const uint32_t b[2]){
    asm volatile("mma.sync.aligned.m16n8k16.row.col.f32.f16.f16.f32 "
                 "{%0,%1,%2,%3}, {%4,%5,%6,%7}, {%8,%9}, {%0,%1,%2,%3};"
                 : "+f"(d[0]),"+f"(d[1]),"+f"(d[2]),"+f"(d[3])
                 : "r"(a[0]),"r"(a[1]),"r"(a[2]),"r"(a[3]),"r"(b[0]),"r"(b[1]));
}
DINL uint2 cvt4h(float4 v){
    union { __half2 h[2]; uint2 u; } p;
    p.h[0] = __floats2half2_rn(v.x, v.y);
    p.h[1] = __floats2half2_rn(v.z, v.w);
    return p.u;
}

// ---------------------------------------------------------------------------
// K0: fp32 -> fp16 conversions (device-global dst, device-side refs)
// ---------------------------------------------------------------------------
__global__ __launch_bounds__(256) void k_cvt_wp(const float* __restrict__ src)
{
    size_t i = ((size_t)blockIdx.x * 256 + threadIdx.x) * 4;
    float4 v = *(const float4*)&src[i];
    *(uint2*)&g_wp_h[i] = cvt4h(v);
}
__global__ __launch_bounds__(256) void k_cvt_wo(const float* __restrict__ src)
{
    size_t i = ((size_t)blockIdx.x * 256 + threadIdx.x) * 4;
    float4 v = *(const float4*)&src[i];
    *(uint2*)&g_wo_h[i] = cvt4h(v);
}
__global__ __launch_bounds__(256) void k_cvt_q(const float* __restrict__ src)
{
    size_t i = ((size_t)blockIdx.x * 256 + threadIdx.x) * 4;   // 900 blocks exact
    float4 v = *(const float4*)&src[i];
    *(uint2*)&g_q_h[i] = cvt4h(v);
}

// ---------------------------------------------------------------------------
// K1: params = half( q_h @ Wp + bp )   [3600,256] x [256,32768]
// BM=128, BN=128, BK=32, 8 warps, fp16 MMA, register prefetch, 3 CTAs/SM.
// ---------------------------------------------------------------------------
__global__ __launch_bounds__(256, 3) void k_params(const float* __restrict__ bp)
{
    __shared__ __half As[128][40];    // [m][k], pad 8
    __shared__ __half Bs[32][136];    // [k][n], pad 8

    const int tx = threadIdx.x;
    const int bn = blockIdx.x;        // 256
    const int bm = blockIdx.y;        // 29
    const int lane = tx & 31, wid = tx >> 5;
    const int g8 = lane >> 2, t4 = lane & 3;
    const int wm = (wid >> 2) * 64, wn = (wid & 3) * 32;

    const int arow = tx >> 1, acol = (tx & 1) * 16;
    const int brow = tx >> 3, bcol = (tx & 7) * 16;
    const int gm = bm * 128 + arow;
    const bool av = (gm < NQ);

    const int lr  = (lane & 7) + ((lane >> 3) & 1) * 8;
    const int lc8 = (lane >> 4) * 8;

    uint4 apre[2], bpre[2];
    #pragma unroll
    for (int i = 0; i < 2; i++)
        apre[i] = av ? *(const uint4*)&g_q_h[(size_t)gm*KD + acol + 8*i]
                     : make_uint4(0u,0u,0u,0u);
    bpre[0] = *(const uint4*)&g_wp_h[(size_t)brow*NPAR + (size_t)bn*128 + bcol];
    bpre[1] = *(const uint4*)&g_wp_h[(size_t)brow*NPAR + (size_t)bn*128 + bcol + 8];

    float acc[4][4][4];
    #pragma unroll
    for (int i=0;i<4;i++) for (int j=0;j<4;j++) for (int q=0;q<4;q++) acc[i][j][q]=0.f;

    #pragma unroll 1
    for (int ks = 0; ks < 8; ks++){
        *(uint4*)&As[arow][acol]     = apre[0];
        *(uint4*)&As[arow][acol + 8] = apre[1];
        *(uint4*)&Bs[brow][bcol]     = bpre[0];
        *(uint4*)&Bs[brow][bcol + 8] = bpre[1];
        __syncthreads();
        if (ks < 7){
            const int k0 = (ks + 1) * 32;
            #pragma unroll
            for (int i = 0; i < 2; i++)
                apre[i] = av ? *(const uint4*)&g_q_h[(size_t)gm*KD + k0 + acol + 8*i]
                             : make_uint4(0u,0u,0u,0u);
            bpre[0] = *(const uint4*)&g_wp_h[(size_t)(k0+brow)*NPAR + (size_t)bn*128 + bcol];
            bpre[1] = *(const uint4*)&g_wp_h[(size_t)(k0+brow)*NPAR + (size_t)bn*128 + bcol + 8];
        }
        #pragma unroll
        for (int kk = 0; kk < 32; kk += 16){
            uint32_t af[4][4], bf[4][2];
            #pragma unroll
            for (int mi = 0; mi < 4; mi++)
                ldsm_x4(af[mi], smem_u32(&As[wm + mi*16 + lr][kk + lc8]));
            #pragma unroll
            for (int nj = 0; nj < 2; nj++){
                uint32_t r[4];
                ldsm_x4_t(r, smem_u32(&Bs[kk + lr][wn + nj*16 + lc8]));
                bf[nj*2+0][0]=r[0]; bf[nj*2+0][1]=r[1];
                bf[nj*2+1][0]=r[2]; bf[nj*2+1][1]=r[3];
            }
            #pragma unroll
            for (int mi = 0; mi < 4; mi++)
                #pragma unroll
                for (int ni = 0; ni < 4; ni++)
                    mma16816(acc[mi][ni], af[mi], bf[ni]);
        }
        __syncthreads();
    }

    #pragma unroll
    for (int mi = 0; mi < 4; mi++){
        int r0 = bm*128 + wm + mi*16 + g8;
        #pragma unroll
        for (int ni = 0; ni < 4; ni++){
            int c = bn*128 + wn + ni*8 + t4*2;
            float2 bv = *(const float2*)&bp[c];
            if (r0 < NQ)
                *(__half2*)&g_params[(size_t)r0*NPAR + c] =
                    __floats2half2_rn(acc[mi][ni][0]+bv.x, acc[mi][ni][1]+bv.y);
            if (r0 + 8 < NQ)
                *(__half2*)&g_params[(size_t)(r0+8)*NPAR + c] =
                    __floats2half2_rn(acc[mi][ni][2]+bv.x, acc[mi][ni][3]+bv.y);
        }
    }
}

// ---------------------------------------------------------------------------
// K2: per-n mixing with fp16 tensor cores (R9 128-thread version, measured
// best). CTA = (gpair, n): 2 groups x 2 warps, 48128B dynamic smem.
// ---------------------------------------------------------------------------
__global__ __launch_bounds__(128, 1) void k_mix2(const float* __restrict__ x)
{
    extern __shared__ __half dsm[];
    __shared__ float sR[16];

    const int gpair = blockIdx.x;   // 0,1
    const int n = blockIdx.y;
    const int tx = threadIdx.x;
    const int lane = tx & 31, wid = tx >> 5;      // wid 0..3
    const int g = wid >> 1, wg = wid & 1;         // local group, warp-in-group
    const int g8 = lane >> 2, t4 = lane & 3;
    const int lr  = (lane & 7) + ((lane >> 3) & 1) * 8;
    const int lc8 = (lane >> 4) * 8;

    // ---- loads (2 groups) ----
    const __half* pp = g_params + (size_t)n * NPAR + (size_t)gpair * 2 * TOT;
    #pragma unroll
    for (int i = 0; i < 8; i++){                 // M: 2g x 64 rows x 8 uint4
        int idx = i*128 + tx, gg = idx >> 9, rem = idx & 511;
        int row = rem >> 3, col = (rem & 7) * 8;
        *(uint4*)&dsm[gg*GSTR + row*72 + col] =
            *(const uint4*)&pp[(size_t)gg*TOT + row*64 + col];
    }
    #pragma unroll
    for (int i = 0; i < 8; i++){                 // S: 2g x 128 rows x 4 uint4
        int idx = i*128 + tx, gg = idx >> 9, rem = idx & 511;
        int row = rem >> 2, col = (rem & 3) * 8;
        *(uint4*)&dsm[gg*GSTR + G_M + row*40 + col] =
            *(const uint4*)&pp[(size_t)gg*TOT + 4096 + row*32 + col];
    }
    const float* xb = x + (size_t)n * 8192 + (size_t)gpair * 2 * 2048;
    #pragma unroll
    for (int i = 0; i < 8; i++){                 // X: 2g x 32 rows x 16 float4
        int idx = i*128 + tx, gg = idx >> 9, rem = idx & 511;
        int row = rem >> 4, col = (rem & 15) * 4;
        float4 v = *(const float4*)&xb[gg*2048 + row*64 + col];
        *(uint2*)&dsm[gg*GSTR + G_M + G_S + row*72 + col] = cvt4h(v);
    }
    __syncthreads();

    __half* Mg = dsm + g*GSTR;
    __half* Sg = Mg + G_M;
    __half* Xg = Sg + G_S;     // aliased as H after GEMM1

    // ---- GEMM1: C1[32,64] ; warp wg owns rows wg*16..+15 ----
    const int m0 = wg * 16;
    float c1[8][4];
    #pragma unroll
    for (int i=0;i<8;i++) for (int q=0;q<4;q++) c1[i][q]=0.f;
    #pragma unroll
    for (int k = 0; k < 64; k += 16){
        uint32_t a[4], b[8][2];
        ldsm_x4(a, smem_u32(&Xg[(m0 + lr)*72 + k + lc8]));
        #pragma unroll
        for (int nj = 0; nj < 4; nj++){
            uint32_t r[4];
            ldsm_x4_t(r, smem_u32(&Mg[(k + lr)*72 + nj*16 + lc8]));
            b[nj*2+0][0]=r[0]; b[nj*2+0][1]=r[1];
            b[nj*2+1][0]=r[2]; b[nj*2+1][1]=r[3];
        }
        #pragma unroll
        for (int ni = 0; ni < 8; ni++) mma16816(c1[ni], a, b[ni]);
    }
    // ---- LN1 over 2048 ----
    float s = 0.f, s2 = 0.f;
    #pragma unroll
    for (int i=0;i<8;i++) for (int q=0;q<4;q++){ s += c1[i][q]; s2 = fmaf(c1[i][q], c1[i][q], s2); }
    #pragma unroll
    for (int off=16; off>0; off>>=1){
        s  += __shfl_xor_sync(0xffffffffu, s,  off);
        s2 += __shfl_xor_sync(0xffffffffu, s2, off);
    }
    if (lane == 0){ sR[wid*2] = s; sR[wid*2+1] = s2; }
    __syncthreads();
    {
        float S1 = sR[g*4+0] + sR[g*4+2];
        float S2 = sR[g*4+1] + sR[g*4+3];
        float mu = S1 * (1.f/2048.f);
        float rstd = rsqrtf(S2 * (1.f/2048.f) - mu*mu + 1e-5f);
        #pragma unroll
        for (int ni = 0; ni < 8; ni++){
            int col = ni*8 + t4*2;
            *(__half2*)&Xg[(m0 + g8)*72 + col] =
                __floats2half2_rn(fmaxf(0.f,(c1[ni][0]-mu)*rstd), fmaxf(0.f,(c1[ni][1]-mu)*rstd));
            *(__half2*)&Xg[(m0 + g8 + 8)*72 + col] =
                __floats2half2_rn(fmaxf(0.f,(c1[ni][2]-mu)*rstd), fmaxf(0.f,(c1[ni][3]-mu)*rstd));
        }
    }
    __syncthreads();

    // ---- GEMM2: C2[128,64] ; warp wg owns rows wg*64..+63 ----
    const int q0 = wg * 64;
    float c2[4][8][4];
    #pragma unroll
    for (int mi=0;mi<4;mi++) for (int ni=0;ni<8;ni++) for (int q=0;q<4;q++) c2[mi][ni][q]=0.f;
    #pragma unroll
    for (int k = 0; k < 32; k += 16){
        uint32_t a2[4][4], b2[8][2];
        #pragma unroll
        for (int mi = 0; mi < 4; mi++)
            ldsm_x4(a2[mi], smem_u32(&Sg[(q0 + mi*16 + lr)*40 + k + lc8]));
        #pragma unroll
        for (int nj = 0; nj < 4; nj++){
            uint32_t r[4];
            ldsm_x4_t(r, smem_u32(&Xg[(k + lr)*72 + nj*16 + lc8]));
            b2[nj*2+0][0]=r[0]; b2[nj*2+0][1]=r[1];
            b2[nj*2+1][0]=r[2]; b2[nj*2+1][1]=r[3];
        }
        #pragma unroll
        for (int mi = 0; mi < 4; mi++)
            #pragma unroll
            for (int ni = 0; ni < 8; ni++)
                mma16816(c2[mi][ni], a2[mi], b2[ni]);
    }
    // ---- LN2 over 8192 ----
    s = 0.f; s2 = 0.f;
    #pragma unroll
    for (int mi=0;mi<4;mi++) for (int ni=0;ni<8;ni++) for (int q=0;q<4;q++){
        s += c2[mi][ni][q]; s2 = fmaf(c2[mi][ni][q], c2[mi][ni][q], s2);
    }
    #pragma unroll
    for (int off=16; off>0; off>>=1){
        s  += __shfl_xor_sync(0xffffffffu, s,  off);
        s2 += __shfl_xor_sync(0xffffffffu, s2, off);
    }
    if (lane == 0){ sR[wid*2] = s; sR[wid*2+1] = s2; }
    __syncthreads();
    float S1 = sR[g*4+0] + sR[g*4+2];
    float S2 = sR[g*4+1] + sR[g*4+3];
    float mu = S1 * (1.f/8192.f);
    float rstd = rsqrtf(S2 * (1.f/8192.f) - mu*mu + 1e-5f);

    __half* outp = g_h2 + (size_t)n*NPAR + (size_t)(gpair*2 + g)*TOT;
    #pragma unroll
    for (int mi = 0; mi < 4; mi++){
        int r0 = q0 + mi*16 + g8;
        #pragma unroll
        for (int ni = 0; ni < 8; ni++){
            int col = ni*8 + t4*2;
            *(__half2*)&outp[r0*64 + col] =
                __floats2half2_rn(fmaxf(0.f,(c2[mi][ni][0]-mu)*rstd), fmaxf(0.f,(c2[mi][ni][1]-mu)*rstd));
            *(__half2*)&outp[(r0+8)*64 + col] =
                __floats2half2_rn(fmaxf(0.f,(c2[mi][ni][2]-mu)*rstd), fmaxf(0.f,(c2[mi][ni][3]-mu)*rstd));
        }
    }
}

// ---------------------------------------------------------------------------
// K3: psum[sk] = h2[:, sk-slice] @ Wo[sk-slice, :]
// BM=128, BN=128, BK=32, split-K=8, register prefetch, 3 CTAs/SM.
// ---------------------------------------------------------------------------
__global__ __launch_bounds__(256, 3) void k_proj()
{
    __shared__ __half As[128][40];
    __shared__ __half Bs[32][136];

    const int tx = threadIdx.x;
    const int bm = blockIdx.x;      // 29
    const int bn = blockIdx.y;      // 2
    const int sk = blockIdx.z;      // 8
    const int lane = tx & 31, wid = tx >> 5;
    const int g8 = lane >> 2, t4 = lane & 3;
    const int wm = (wid >> 2) * 64, wn = (wid & 3) * 32;

    const int arow = tx >> 1, acol = (tx & 1) * 16;
    const int brow = tx >> 3, bcol = (tx & 7) * 16;
    const int gm = bm * 128 + arow;
    const bool av = (gm < NQ);
    const int kbase = sk * 4096;

    const int lr  = (lane & 7) + ((lane >> 3) & 1) * 8;
    const int lc8 = (lane >> 4) * 8;

    uint4 apre[2], bpre[2];
    #pragma unroll
    for (int i = 0; i < 2; i++)
        apre[i] = av ? *(const uint4*)&g_h2[(size_t)gm*NPAR + kbase + acol + 8*i]
                     : make_uint4(0u,0u,0u,0u);
    bpre[0] = *(const uint4*)&g_wo_h[(size_t)(kbase+brow)*KD + bn*128 + bcol];
    bpre[1] = *(const uint4*)&g_wo_h[(size_t)(kbase+brow)*KD + bn*128 + bcol + 8];

    float acc[4][4][4];
    #pragma unroll
    for (int i=0;i<4;i++) for (int j=0;j<4;j++) for (int q=0;q<4;q++) acc[i][j][q]=0.f;

    #pragma unroll 1
    for (int ks = 0; ks < 128; ks++){
        *(uint4*)&As[arow][acol]     = apre[0];
        *(uint4*)&As[arow][acol + 8] = apre[1];
        *(uint4*)&Bs[brow][bcol]     = bpre[0];
        *(uint4*)&Bs[brow][bcol + 8] = bpre[1];
        __syncthreads();
        if (ks < 127){
            const int k0 = kbase + (ks + 1) * 32;
            #pragma unroll
            for (int i = 0; i < 2; i++)
                apre[i] = av ? *(const uint4*)&g_h2[(size_t)gm*NPAR + k0 + acol + 8*i]
                             : make_uint4(0u,0u,0u,0u);
            bpre[0] = *(const uint4*)&g_wo_h[(size_t)(k0+brow)*KD + bn*128 + bcol];
            bpre[1] = *(const uint4*)&g_wo_h[(size_t)(k0+brow)*KD + bn*128 + bcol + 8];
        }
        #pragma unroll
        for (int kk = 0; kk < 32; kk += 16){
            uint32_t af[4][4], bf[4][2];
            #pragma unroll
            for (int mi = 0; mi < 4; mi++)
                ldsm_x4(af[mi], smem_u32(&As[wm + mi*16 + lr][kk + lc8]));
            #pragma unroll
            for (int nj = 0; nj < 2; nj++){
                uint32_t r[4];
                ldsm_x4_t(r, smem_u32(&Bs[kk + lr][wn + nj*16 + lc8]));
                bf[nj*2+0][0]=r[0]; bf[nj*2+0][1]=r[1];
                bf[nj*2+1][0]=r[2]; bf[nj*2+1][1]=r[3];
            }
            #pragma unroll
            for (int mi = 0; mi < 4; mi++)
                #pragma unroll
                for (int ni = 0; ni < 4; ni++)
                    mma16816(acc[mi][ni], af[mi], bf[ni]);
        }
        __syncthreads();
    }

    #pragma unroll
    for (int mi = 0; mi < 4; mi++){
        int r0 = bm*128 + wm + mi*16 + g8;
        #pragma unroll
        for (int ni = 0; ni < 4; ni++){
            int c = bn*128 + wn + ni*8 + t4*2;
            if (r0 < NQ)
                *(float2*)&g_psum[((size_t)sk*NQ + r0)*KD + c] =
                    make_float2(acc[mi][ni][0], acc[mi][ni][1]);
            if (r0 + 8 < NQ)
                *(float2*)&g_psum[((size_t)sk*NQ + (r0+8))*KD + c] =
                    make_float2(acc[mi][ni][2], acc[mi][ni][3]);
        }
    }
}

// ---------------------------------------------------------------------------
// K4: out = query + bo + sum_sk psum[sk]
// ---------------------------------------------------------------------------
__global__ __launch_bounds__(256) void k_reduce(const float* __restrict__ query,
                                                const float* __restrict__ bo,
                                                float* __restrict__ out)
{
    int idx = blockIdx.x * 256 + threadIdx.x;
    float v = query[idx] + bo[idx & 255];
    #pragma unroll
    for (int s = 0; s < SPLITK; s++)
        v += g_psum[(size_t)s * NQ * KD + idx];
    out[idx] = v;
}

// ---------------------------------------------------------------------------
extern "C" void kernel_launch(void* const* d_in, const int* in_sizes, int n_in,
                              void* d_out, int out_size)
{
    const float* x     = (const float*)d_in[0];
    const float* query = (const float*)d_in[1];
    const float* Wp    = (const float*)d_in[2];
    const float* bp    = (const float*)d_in[3];
    const float* Wo    = (const float*)d_in[4];
    const float* bo    = (const float*)d_in[5];
    float* out = (float*)d_out;

    k_cvt_wp<<<WN_ELEMS/1024, 256>>>(Wp);
    k_cvt_wo<<<WN_ELEMS/1024, 256>>>(Wo);
    k_cvt_q<<<(NQ*KD)/1024, 256>>>(query);
    k_params<<<dim3(256, 29), 256>>>(bp);
    k_mix2<<<dim3(2, 3600), 128, K2_SMEM>>>(x);
    k_proj<<<dim3(29, 2, SPLITK), 256>>>();
    k_reduce<<<3600, 256>>>(query, bo, out);
}

// round 17
// speedup vs baseline: 2.8062x; 2.8062x over previous
#include <cuda_runtime.h>
#include <cuda_fp16.h>
#include <cstdint>

#define DINL __device__ __forceinline__

namespace {
constexpr int NQ   = 3600;    // B*Q
constexpr int KD   = 256;     // query dim
constexpr int NPAR = 32768;   // G * TOTAL
constexpr int TOT  = 8192;
constexpr int SPLITK = 8;
constexpr int WN_ELEMS = 8388608;         // 256*32768 == 32768*256
// K2 smem layout (halfs): per group M[64][72], S[128][40], X/H[32][72]
constexpr int G_M = 64 * 72;              // 4608
constexpr int G_S = 128 * 40;             // 5120
constexpr int G_X = 32 * 72;              // 2304
constexpr int GSTR = G_M + G_S + G_X;     // 12032 halfs
constexpr int K2_SMEM = 2 * GSTR * 2;     // 48128 bytes  (<= 49152 default limit)
}

// scratch (device globals: allocation-free)
__device__ __half g_params[(size_t)NQ * NPAR];              // 236 MB
__device__ __half g_h2[(size_t)NQ * NPAR];                  // 236 MB
__device__ float  g_psum[(size_t)SPLITK * NQ * KD];         // 29.5 MB
__device__ __half g_wp_h[(size_t)WN_ELEMS];                 // 16.7 MB
__device__ __half g_wo_h[(size_t)WN_ELEMS];                 // 16.7 MB
__device__ __half g_q_h[(size_t)NQ * KD];                   // 1.8 MB

DINL uint32_t smem_u32(const void* p){ return (uint32_t)__cvta_generic_to_shared(p); }

DINL void ldsm_x4(uint32_t r[4], uint32_t a){
    asm volatile("ldmatrix.sync.aligned.m8n8.x4.shared.b16 {%0,%1,%2,%3}, [%4];"
                 : "=r"(r[0]),"=r"(r[1]),"=r"(r[2]),"=r"(r[3]) : "r"(a));
}
DINL void ldsm_x4_t(uint32_t r[4], uint32_t a){
    asm volatile("ldmatrix.sync.aligned.m8n8.x4.trans.shared.b16 {%0,%1,%2,%3}, [%4];"
                 : "=r"(r[0]),"=r"(r[1]),"=r"(r[2]),"=r"(r[3]) : "r"(a));
}
DINL void mma16816(float d[4], const uint32_t a[4], const uint32_t b[2]){
    asm volatile("mma.sync.aligned.m16n8k16.row.col.f32.f16.f16.f32 "
                 "{%0,%1,%2,%3}, {%4,%5,%6,%7}, {%8,%9}, {%0,%1,%2,%3};"
                 : "+f"(d[0]),"+f"(d[1]),"+f"(d[2]),"+f"(d[3])
                 : "r"(a[0]),"r"(a[1]),"r"(a[2]),"r"(a[3]),"r"(b[0]),"r"(b[1]));
}
DINL uint2 cvt4h(float4 v){
    union { __half2 h[2]; uint2 u; } p;
    p.h[0] = __floats2half2_rn(v.x, v.y);
    p.h[1] = __floats2half2_rn(v.z, v.w);
    return p.u;
}

// ---------------------------------------------------------------------------
// K0: fp32 -> fp16 conversions (device-global dst, device-side refs)
// ---------------------------------------------------------------------------
__global__ __launch_bounds__(256) void k_cvt_wp(const float* __restrict__ src)
{
    size_t i = ((size_t)blockIdx.x * 256 + threadIdx.x) * 4;
    float4 v = *(const float4*)&src[i];
    *(uint2*)&g_wp_h[i] = cvt4h(v);
}
__global__ __launch_bounds__(256) void k_cvt_wo(const float* __restrict__ src)
{
    size_t i = ((size_t)blockIdx.x * 256 + threadIdx.x) * 4;
    float4 v = *(const float4*)&src[i];
    *(uint2*)&g_wo_h[i] = cvt4h(v);
}
__global__ __launch_bounds__(256) void k_cvt_q(const float* __restrict__ src)
{
    size_t i = ((size_t)blockIdx.x * 256 + threadIdx.x) * 4;   // 900 blocks exact
    float4 v = *(const float4*)&src[i];
    *(uint2*)&g_q_h[i] = cvt4h(v);
}

// ---------------------------------------------------------------------------
// K1: params = half( q_h @ Wp + bp )   [3600,256] x [256,32768]
// BM=128, BN=128, BK=32, 8 warps (2m x 4n), fp16 MMA.
// Double-buffered smem: ONE __syncthreads per k-chunk; LDG prefetch issued
// before the barrier. No launch bounds (regs ~90 -> 2 CTAs/SM, no spills).
// ---------------------------------------------------------------------------
__global__ __launch_bounds__(256) void k_params(const float* __restrict__ bp)
{
    __shared__ __half As[2][128][40];    // [m][k], pad 8    (20480 B)
    __shared__ __half Bs[2][32][136];    // [k][n], pad 8    (17408 B)

    const int tx = threadIdx.x;
    const int bn = blockIdx.x;        // 256
    const int bm = blockIdx.y;        // 29
    const int lane = tx & 31, wid = tx >> 5;
    const int g8 = lane >> 2, t4 = lane & 3;
    const int wm = (wid >> 2) * 64, wn = (wid & 3) * 32;

    const int arow = tx >> 1, acol = (tx & 1) * 16;
    const int brow = tx >> 3, bcol = (tx & 7) * 16;
    const int gm = bm * 128 + arow;
    const bool av = (gm < NQ);

    const int lr  = (lane & 7) + ((lane >> 3) & 1) * 8;
    const int lc8 = (lane >> 4) * 8;

    uint4 apre[2], bpre[2];
    #pragma unroll
    for (int i = 0; i < 2; i++)
        apre[i] = av ? *(const uint4*)&g_q_h[(size_t)gm*KD + acol + 8*i]
                     : make_uint4(0u,0u,0u,0u);
    bpre[0] = *(const uint4*)&g_wp_h[(size_t)brow*NPAR + (size_t)bn*128 + bcol];
    bpre[1] = *(const uint4*)&g_wp_h[(size_t)brow*NPAR + (size_t)bn*128 + bcol + 8];

    // stage 0 fill
    *(uint4*)&As[0][arow][acol]     = apre[0];
    *(uint4*)&As[0][arow][acol + 8] = apre[1];
    *(uint4*)&Bs[0][brow][bcol]     = bpre[0];
    *(uint4*)&Bs[0][brow][bcol + 8] = bpre[1];

    float acc[4][4][4];
    #pragma unroll
    for (int i=0;i<4;i++) for (int j=0;j<4;j++) for (int q=0;q<4;q++) acc[i][j][q]=0.f;

    int s = 0;
    #pragma unroll 1
    for (int ks = 0; ks < 8; ks++){
        if (ks < 7){
            const int k0 = (ks + 1) * 32;
            #pragma unroll
            for (int i = 0; i < 2; i++)
                apre[i] = av ? *(const uint4*)&g_q_h[(size_t)gm*KD + k0 + acol + 8*i]
                             : make_uint4(0u,0u,0u,0u);
            bpre[0] = *(const uint4*)&g_wp_h[(size_t)(k0+brow)*NPAR + (size_t)bn*128 + bcol];
            bpre[1] = *(const uint4*)&g_wp_h[(size_t)(k0+brow)*NPAR + (size_t)bn*128 + bcol + 8];
        }
        __syncthreads();      // stage s ready (stores from previous iteration)
        #pragma unroll
        for (int kk = 0; kk < 32; kk += 16){
            uint32_t af[4][4], bf[4][2];
            #pragma unroll
            for (int mi = 0; mi < 4; mi++)
                ldsm_x4(af[mi], smem_u32(&As[s][wm + mi*16 + lr][kk + lc8]));
            #pragma unroll
            for (int nj = 0; nj < 2; nj++){
                uint32_t r[4];
                ldsm_x4_t(r, smem_u32(&Bs[s][kk + lr][wn + nj*16 + lc8]));
                bf[nj*2+0][0]=r[0]; bf[nj*2+0][1]=r[1];
                bf[nj*2+1][0]=r[2]; bf[nj*2+1][1]=r[3];
            }
            #pragma unroll
            for (int mi = 0; mi < 4; mi++)
                #pragma unroll
                for (int ni = 0; ni < 4; ni++)
                    mma16816(acc[mi][ni], af[mi], bf[ni]);
        }
        if (ks < 7){
            *(uint4*)&As[s^1][arow][acol]     = apre[0];
            *(uint4*)&As[s^1][arow][acol + 8] = apre[1];
            *(uint4*)&Bs[s^1][brow][bcol]     = bpre[0];
            *(uint4*)&Bs[s^1][brow][bcol + 8] = bpre[1];
        }
        s ^= 1;
    }

    #pragma unroll
    for (int mi = 0; mi < 4; mi++){
        int r0 = bm*128 + wm + mi*16 + g8;
        #pragma unroll
        for (int ni = 0; ni < 4; ni++){
            int c = bn*128 + wn + ni*8 + t4*2;
            float2 bv = *(const float2*)&bp[c];
            if (r0 < NQ)
                *(__half2*)&g_params[(size_t)r0*NPAR + c] =
                    __floats2half2_rn(acc[mi][ni][0]+bv.x, acc[mi][ni][1]+bv.y);
            if (r0 + 8 < NQ)
                *(__half2*)&g_params[(size_t)(r0+8)*NPAR + c] =
                    __floats2half2_rn(acc[mi][ni][2]+bv.x, acc[mi][ni][3]+bv.y);
        }
    }
}

// ---------------------------------------------------------------------------
// K2: per-n mixing with fp16 tensor cores (R9 128-thread version, measured
// best). CTA = (gpair, n): 2 groups x 2 warps, 48128B dynamic smem.
// ---------------------------------------------------------------------------
__global__ __launch_bounds__(128, 1) void k_mix2(const float* __restrict__ x)
{
    extern __shared__ __half dsm[];
    __shared__ float sR[16];

    const int gpair = blockIdx.x;   // 0,1
    const int n = blockIdx.y;
    const int tx = threadIdx.x;
    const int lane = tx & 31, wid = tx >> 5;      // wid 0..3
    const int g = wid >> 1, wg = wid & 1;         // local group, warp-in-group
    const int g8 = lane >> 2, t4 = lane & 3;
    const int lr  = (lane & 7) + ((lane >> 3) & 1) * 8;
    const int lc8 = (lane >> 4) * 8;

    // ---- loads (2 groups) ----
    const __half* pp = g_params + (size_t)n * NPAR + (size_t)gpair * 2 * TOT;
    #pragma unroll
    for (int i = 0; i < 8; i++){                 // M: 2g x 64 rows x 8 uint4
        int idx = i*128 + tx, gg = idx >> 9, rem = idx & 511;
        int row = rem >> 3, col = (rem & 7) * 8;
        *(uint4*)&dsm[gg*GSTR + row*72 + col] =
            *(const uint4*)&pp[(size_t)gg*TOT + row*64 + col];
    }
    #pragma unroll
    for (int i = 0; i < 8; i++){                 // S: 2g x 128 rows x 4 uint4
        int idx = i*128 + tx, gg = idx >> 9, rem = idx & 511;
        int row = rem >> 2, col = (rem & 3) * 8;
        *(uint4*)&dsm[gg*GSTR + G_M + row*40 + col] =
            *(const uint4*)&pp[(size_t)gg*TOT + 4096 + row*32 + col];
    }
    const float* xb = x + (size_t)n * 8192 + (size_t)gpair * 2 * 2048;
    #pragma unroll
    for (int i = 0; i < 8; i++){                 // X: 2g x 32 rows x 16 float4
        int idx = i*128 + tx, gg = idx >> 9, rem = idx & 511;
        int row = rem >> 4, col = (rem & 15) * 4;
        float4 v = *(const float4*)&xb[gg*2048 + row*64 + col];
        *(uint2*)&dsm[gg*GSTR + G_M + G_S + row*72 + col] = cvt4h(v);
    }
    __syncthreads();

    __half* Mg = dsm + g*GSTR;
    __half* Sg = Mg + G_M;
    __half* Xg = Sg + G_S;     // aliased as H after GEMM1

    // ---- GEMM1: C1[32,64] ; warp wg owns rows wg*16..+15 ----
    const int m0 = wg * 16;
    float c1[8][4];
    #pragma unroll
    for (int i=0;i<8;i++) for (int q=0;q<4;q++) c1[i][q]=0.f;
    #pragma unroll
    for (int k = 0; k < 64; k += 16){
        uint32_t a[4], b[8][2];
        ldsm_x4(a, smem_u32(&Xg[(m0 + lr)*72 + k + lc8]));
        #pragma unroll
        for (int nj = 0; nj < 4; nj++){
            uint32_t r[4];
            ldsm_x4_t(r, smem_u32(&Mg[(k + lr)*72 + nj*16 + lc8]));
            b[nj*2+0][0]=r[0]; b[nj*2+0][1]=r[1];
            b[nj*2+1][0]=r[2]; b[nj*2+1][1]=r[3];
        }
        #pragma unroll
        for (int ni = 0; ni < 8; ni++) mma16816(c1[ni], a, b[ni]);
    }
    // ---- LN1 over 2048 ----
    float s = 0.f, s2 = 0.f;
    #pragma unroll
    for (int i=0;i<8;i++) for (int q=0;q<4;q++){ s += c1[i][q]; s2 = fmaf(c1[i][q], c1[i][q], s2); }
    #pragma unroll
    for (int off=16; off>0; off>>=1){
        s  += __shfl_xor_sync(0xffffffffu, s,  off);
        s2 += __shfl_xor_sync(0xffffffffu, s2, off);
    }
    if (lane == 0){ sR[wid*2] = s; sR[wid*2+1] = s2; }
    __syncthreads();
    {
        float S1 = sR[g*4+0] + sR[g*4+2];
        float S2 = sR[g*4+1] + sR[g*4+3];
        float mu = S1 * (1.f/2048.f);
        float rstd = rsqrtf(S2 * (1.f/2048.f) - mu*mu + 1e-5f);
        #pragma unroll
        for (int ni = 0; ni < 8; ni++){
            int col = ni*8 + t4*2;
            *(__half2*)&Xg[(m0 + g8)*72 + col] =
                __floats2half2_rn(fmaxf(0.f,(c1[ni][0]-mu)*rstd), fmaxf(0.f,(c1[ni][1]-mu)*rstd));
            *(__half2*)&Xg[(m0 + g8 + 8)*72 + col] =
                __floats2half2_rn(fmaxf(0.f,(c1[ni][2]-mu)*rstd), fmaxf(0.f,(c1[ni][3]-mu)*rstd));
        }
    }
    __syncthreads();

    // ---- GEMM2: C2[128,64] ; warp wg owns rows wg*64..+63 ----
    const int q0 = wg * 64;
    float c2[4][8][4];
    #pragma unroll
    for (int mi=0;mi<4;mi++) for (int ni=0;ni<8;ni++) for (int q=0;q<4;q++) c2[mi][ni][q]=0.f;
    #pragma unroll
    for (int k = 0; k < 32; k += 16){
        uint32_t a2[4][4], b2[8][2];
        #pragma unroll
        for (int mi = 0; mi < 4; mi++)
            ldsm_x4(a2[mi], smem_u32(&Sg[(q0 + mi*16 + lr)*40 + k + lc8]));
        #pragma unroll
        for (int nj = 0; nj < 4; nj++){
            uint32_t r[4];
            ldsm_x4_t(r, smem_u32(&Xg[(k + lr)*72 + nj*16 + lc8]));
            b2[nj*2+0][0]=r[0]; b2[nj*2+0][1]=r[1];
            b2[nj*2+1][0]=r[2]; b2[nj*2+1][1]=r[3];
        }
        #pragma unroll
        for (int mi = 0; mi < 4; mi++)
            #pragma unroll
            for (int ni = 0; ni < 8; ni++)
                mma16816(c2[mi][ni], a2[mi], b2[ni]);
    }
    // ---- LN2 over 8192 ----
    s = 0.f; s2 = 0.f;
    #pragma unroll
    for (int mi=0;mi<4;mi++) for (int ni=0;ni<8;ni++) for (int q=0;q<4;q++){
        s += c2[mi][ni][q]; s2 = fmaf(c2[mi][ni][q], c2[mi][ni][q], s2);
    }
    #pragma unroll
    for (int off=16; off>0; off>>=1){
        s  += __shfl_xor_sync(0xffffffffu, s,  off);
        s2 += __shfl_xor_sync(0xffffffffu, s2, off);
    }
    if (lane == 0){ sR[wid*2] = s; sR[wid*2+1] = s2; }
    __syncthreads();
    float S1 = sR[g*4+0] + sR[g*4+2];
    float S2 = sR[g*4+1] + sR[g*4+3];
    float mu = S1 * (1.f/8192.f);
    float rstd = rsqrtf(S2 * (1.f/8192.f) - mu*mu + 1e-5f);

    __half* outp = g_h2 + (size_t)n*NPAR + (size_t)(gpair*2 + g)*TOT;
    #pragma unroll
    for (int mi = 0; mi < 4; mi++){
        int r0 = q0 + mi*16 + g8;
        #pragma unroll
        for (int ni = 0; ni < 8; ni++){
            int col = ni*8 + t4*2;
            *(__half2*)&outp[r0*64 + col] =
                __floats2half2_rn(fmaxf(0.f,(c2[mi][ni][0]-mu)*rstd), fmaxf(0.f,(c2[mi][ni][1]-mu)*rstd));
            *(__half2*)&outp[(r0+8)*64 + col] =
                __floats2half2_rn(fmaxf(0.f,(c2[mi][ni][2]-mu)*rstd), fmaxf(0.f,(c2[mi][ni][3]-mu)*rstd));
        }
    }
}

// ---------------------------------------------------------------------------
// K3: psum[sk] = h2[:, sk-slice] @ Wo[sk-slice, :]
// BM=128, BN=128, BK=32, split-K=8, double-buffered smem, one sync/chunk.
// ---------------------------------------------------------------------------
__global__ __launch_bounds__(256) void k_proj()
{
    __shared__ __half As[2][128][40];
    __shared__ __half Bs[2][32][136];

    const int tx = threadIdx.x;
    const int bm = blockIdx.x;      // 29
    const int bn = blockIdx.y;      // 2
    const int sk = blockIdx.z;      // 8
    const int lane = tx & 31, wid = tx >> 5;
    const int g8 = lane >> 2, t4 = lane & 3;
    const int wm = (wid >> 2) * 64, wn = (wid & 3) * 32;

    const int arow = tx >> 1, acol = (tx & 1) * 16;
    const int brow = tx >> 3, bcol = (tx & 7) * 16;
    const int gm = bm * 128 + arow;
    const bool av = (gm < NQ);
    const int kbase = sk * 4096;

    const int lr  = (lane & 7) + ((lane >> 3) & 1) * 8;
    const int lc8 = (lane >> 4) * 8;

    uint4 apre[2], bpre[2];
    #pragma unroll
    for (int i = 0; i < 2; i++)
        apre[i] = av ? *(const uint4*)&g_h2[(size_t)gm*NPAR + kbase + acol + 8*i]
                     : make_uint4(0u,0u,0u,0u);
    bpre[0] = *(const uint4*)&g_wo_h[(size_t)(kbase+brow)*KD + bn*128 + bcol];
    bpre[1] = *(const uint4*)&g_wo_h[(size_t)(kbase+brow)*KD + bn*128 + bcol + 8];

    *(uint4*)&As[0][arow][acol]     = apre[0];
    *(uint4*)&As[0][arow][acol + 8] = apre[1];
    *(uint4*)&Bs[0][brow][bcol]     = bpre[0];
    *(uint4*)&Bs[0][brow][bcol + 8] = bpre[1];

    float acc[4][4][4];
    #pragma unroll
    for (int i=0;i<4;i++) for (int j=0;j<4;j++) for (int q=0;q<4;q++) acc[i][j][q]=0.f;

    int s = 0;
    #pragma unroll 1
    for (int ks = 0; ks < 128; ks++){
        if (ks < 127){
            const int k0 = kbase + (ks + 1) * 32;
            #pragma unroll
            for (int i = 0; i < 2; i++)
                apre[i] = av ? *(const uint4*)&g_h2[(size_t)gm*NPAR + k0 + acol + 8*i]
                             : make_uint4(0u,0u,0u,0u);
            bpre[0] = *(const uint4*)&g_wo_h[(size_t)(k0+brow)*KD + bn*128 + bcol];
            bpre[1] = *(const uint4*)&g_wo_h[(size_t)(k0+brow)*KD + bn*128 + bcol + 8];
        }
        __syncthreads();      // stage s ready
        #pragma unroll
        for (int kk = 0; kk < 32; kk += 16){
            uint32_t af[4][4], bf[4][2];
            #pragma unroll
            for (int mi = 0; mi < 4; mi++)
                ldsm_x4(af[mi], smem_u32(&As[s][wm + mi*16 + lr][kk + lc8]));
            #pragma unroll
            for (int nj = 0; nj < 2; nj++){
                uint32_t r[4];
                ldsm_x4_t(r, smem_u32(&Bs[s][kk + lr][wn + nj*16 + lc8]));
                bf[nj*2+0][0]=r[0]; bf[nj*2+0][1]=r[1];
                bf[nj*2+1][0]=r[2]; bf[nj*2+1][1]=r[3];
            }
            #pragma unroll
            for (int mi = 0; mi < 4; mi++)
                #pragma unroll
                for (int ni = 0; ni < 4; ni++)
                    mma16816(acc[mi][ni], af[mi], bf[ni]);
        }
        if (ks < 127){
            *(uint4*)&As[s^1][arow][acol]     = apre[0];
            *(uint4*)&As[s^1][arow][acol + 8] = apre[1];
            *(uint4*)&Bs[s^1][brow][bcol]     = bpre[0];
            *(uint4*)&Bs[s^1][brow][bcol + 8] = bpre[1];
        }
        s ^= 1;
    }

    #pragma unroll
    for (int mi = 0; mi < 4; mi++){
        int r0 = bm*128 + wm + mi*16 + g8;
        #pragma unroll
        for (int ni = 0; ni < 4; ni++){
            int c = bn*128 + wn + ni*8 + t4*2;
            if (r0 < NQ)
                *(float2*)&g_psum[((size_t)sk*NQ + r0)*KD + c] =
                    make_float2(acc[mi][ni][0], acc[mi][ni][1]);
            if (r0 + 8 < NQ)
                *(float2*)&g_psum[((size_t)sk*NQ + (r0+8))*KD + c] =
                    make_float2(acc[mi][ni][2], acc[mi][ni][3]);
        }
    }
}

// ---------------------------------------------------------------------------
// K4: out = query + bo + sum_sk psum[sk]
// ---------------------------------------------------------------------------
__global__ __launch_bounds__(256) void k_reduce(const float* __restrict__ query,
                                                const float* __restrict__ bo,
                                                float* __restrict__ out)
{
    int idx = blockIdx.x * 256 + threadIdx.x;
    float v = query[idx] + bo[idx & 255];
    #pragma unroll
    for (int s = 0; s < SPLITK; s++)
        v += g_psum[(size_t)s * NQ * KD + idx];
    out[idx] = v;
}

// ---------------------------------------------------------------------------
extern "C" void kernel_launch(void* const* d_in, const int* in_sizes, int n_in,
                              void* d_out, int out_size)
{
    const float* x     = (const float*)d_in[0];
    const float* query = (const float*)d_in[1];
    const float* Wp    = (const float*)d_in[2];
    const float* bp    = (const float*)d_in[3];
    const float* Wo    = (const float*)d_in[4];
    const float* bo    = (const float*)d_in[5];
    float* out = (float*)d_out;

    k_cvt_wp<<<WN_ELEMS/1024, 256>>>(Wp);
    k_cvt_wo<<<WN_ELEMS/1024, 256>>>(Wo);
    k_cvt_q<<<(NQ*KD)/1024, 256>>>(query);
    k_params<<<dim3(256, 29), 256>>>(bp);
    k_mix2<<<dim3(2, 3600), 128, K2_SMEM>>>(x);
    k_proj<<<dim3(29, 2, SPLITK), 256>>>();
    k_reduce<<<3600, 256>>>(query, bo, out);
}